// round 15
// baseline (speedup 1.0000x reference)
#include <cuda_runtime.h>
#include <math.h>

#define T_      2048
#define HID_    2560
#define H_      40
#define NOPE_   64
#define ROPE_   32
#define VDIM_   64
#define QLORA_  768
#define KVLORA_ 256
#define DQK     288
#define QHD     96
#define EPS_    1e-5f

// ---------------- scratch ----------------
__device__ float sc_qa  [T_ * QLORA_];
__device__ float sc_qan [T_ * QLORA_];
__device__ float sc_q   [T_ * H_ * QHD];
__device__ float sc_lat [T_ * DQK];
__device__ float sc_kin [T_ * DQK];
__device__ float sc_qin [(size_t)T_ * H_ * DQK];
__device__ float sc_olat[(size_t)T_ * H_ * KVLORA_];
__device__ float sc_ov  [T_ * H_ * VDIM_];

// ---------------- tf32 / mma / cp.async helpers ----------------
__device__ __forceinline__ unsigned tf32c(float x) {
    unsigned u;
    asm("cvt.rna.tf32.f32 %0, %1;" : "=r"(u) : "f"(x));
    return u;
}
__device__ __forceinline__ float tf32f(float x) { return __uint_as_float(tf32c(x)); }
__device__ __forceinline__ void mma8(float c[4], const unsigned a[4], unsigned b0, unsigned b1) {
    asm volatile(
        "mma.sync.aligned.m16n8k8.row.col.f32.tf32.tf32.f32 "
        "{%0,%1,%2,%3},{%4,%5,%6,%7},{%8,%9},{%0,%1,%2,%3};\n"
        : "+f"(c[0]), "+f"(c[1]), "+f"(c[2]), "+f"(c[3])
        : "r"(a[0]), "r"(a[1]), "r"(a[2]), "r"(a[3]), "r"(b0), "r"(b1));
}
__device__ __forceinline__ void cp16(unsigned dst, const void* src, int sz) {
    asm volatile("cp.async.ca.shared.global [%0], [%1], 16, %2;\n"
                 :: "r"(dst), "l"(src), "r"(sz));
}
#define CP_COMMIT() asm volatile("cp.async.commit_group;\n" ::: "memory")
#define CP_WAIT(n)  asm volatile("cp.async.wait_group %0;\n" :: "n"(n) : "memory")

// ---------------- tf32 GEMM BMxBNx16, cp.async 4-stage pipeline ----------------
#define NST 4
#define ALD 20
#define GEMM_SMEM(BM,BN) ((NST * ((BM) * ALD) + NST * (16 * ((BN) == 128 ? 136 : 72))) * 4)

template<int BM, int BN, bool RC, bool DUAL>
__global__ void __launch_bounds__(256, 2)
tgemm_ca(const float* __restrict__ A, const float* __restrict__ B,
         float* __restrict__ C,
         int M, int N, int K, int lda, int ldb, int ldc,
         long sA, long sB, long sC,
         const float* __restrict__ B2, float* __restrict__ C2,
         int N2, int ldb2, int ldc2)
{
    constexpr int WARPS_M = BM / 32;
    constexpr int WN  = BN / (8 / WARPS_M);
    constexpr int NI  = WN / 8;
    constexpr int BLD = (BN == 128) ? 136 : 72;
    constexpr int AST = BM * ALD;
    constexpr int BST = 16 * BLD;
    extern __shared__ float smem[];
    float* Asm = smem;
    float* Bsm = smem + NST * AST;

    const int bm0 = blockIdx.y * BM;
    const int bn0 = blockIdx.x * BN;

    const float* Ab;
    const float* Bb;
    float*       Cb;
    if (DUAL && blockIdx.z == 1) {
        if (bn0 >= N2) return;
        Ab = A; Bb = B2; Cb = C2;
        N = N2; ldb = ldb2; ldc = ldc2;
    } else {
        Ab = A + (long)blockIdx.z * sA;
        Bb = B + (long)blockIdx.z * sB;
        Cb = C + (long)blockIdx.z * sC;
    }

    const int tid = threadIdx.x;
    const int w    = tid >> 5;
    const int lane = tid & 31;
    const int lq   = lane >> 2;
    const int lr   = lane & 3;
    const int wm0  = (w % WARPS_M) * 32;
    const int wn0  = (w / WARPS_M) * WN;

    const int a_row = (BM == 128) ? (tid >> 1) : (tid >> 2);
    const int a_k0  = (BM == 128) ? (tid & 1) * 8 : (tid & 3) * 4;
    const int b_r0  = (BN == 128) ? (tid >> 5) : (tid >> 4);
    const int b_c0  = (BN == 128) ? (tid & 31) * 4 : (tid & 15) * 4;
    const int b_sz  = (bn0 + b_c0 < N) ? 16 : 0;

    const unsigned a_dst0 = (unsigned)__cvta_generic_to_shared(Asm) + (a_row * ALD + a_k0) * 4;
    const unsigned b_dst0 = (unsigned)__cvta_generic_to_shared(Bsm) + (b_r0 * BLD + b_c0) * 4;

    float acc[2][NI][4];
#pragma unroll
    for (int mi = 0; mi < 2; mi++)
#pragma unroll
        for (int ni = 0; ni < NI; ni++)
#pragma unroll
            for (int r = 0; r < 4; r++) acc[mi][ni][r] = 0.f;

    const int nc = K / 16;

#pragma unroll
    for (int s = 0; s < NST - 1; s++) {
        if (s < nc) {
            const int k0 = s * 16;
            const float* ap = Ab + (long)(bm0 + a_row) * lda + k0 + a_k0;
            cp16(a_dst0 + s * AST * 4, ap, 16);
            if (BM == 128) cp16(a_dst0 + s * AST * 4 + 16, ap + 4, 16);
            const float* bp = Bb + (long)(k0 + b_r0) * ldb + bn0 + b_c0;
            cp16(b_dst0 + s * BST * 4, bp, b_sz);
            if (BN == 128) cp16(b_dst0 + s * BST * 4 + 8 * BLD * 4, bp + 8 * ldb, b_sz);
        }
        CP_COMMIT();
    }

    int buf = 0;
    for (int c = 0; c < nc; c++) {
        CP_WAIT(NST - 2);
        __syncthreads();

        const float* Ab_s = Asm + buf * AST;
        const float* Bb_s = Bsm + buf * BST;
#pragma unroll
        for (int ks = 0; ks < 2; ks++) {
            const int kb = ks * 8;
            unsigned afr[2][4];
#pragma unroll
            for (int mi = 0; mi < 2; mi++) {
                const float* r0 = Ab_s + (wm0 + 16 * mi + lq) * ALD + kb + lr;
                afr[mi][0] = tf32c(r0[0]);
                afr[mi][1] = tf32c(r0[8 * ALD]);
                afr[mi][2] = tf32c(r0[4]);
                afr[mi][3] = tf32c(r0[8 * ALD + 4]);
            }
            const float* brow0 = Bb_s + (kb + lr) * BLD + wn0 + lq;
            const float* brow1 = brow0 + 4 * BLD;
#pragma unroll
            for (int ni = 0; ni < NI; ni++) {
                unsigned b0 = tf32c(brow0[ni * 8]);
                unsigned b1 = tf32c(brow1[ni * 8]);
                mma8(acc[0][ni], afr[0], b0, b1);
                mma8(acc[1][ni], afr[1], b0, b1);
            }
        }

        const int cs = c + NST - 1;
        if (cs < nc) {
            const int st = cs % NST;
            const int k0 = cs * 16;
            const float* ap = Ab + (long)(bm0 + a_row) * lda + k0 + a_k0;
            cp16(a_dst0 + st * AST * 4, ap, 16);
            if (BM == 128) cp16(a_dst0 + st * AST * 4 + 16, ap + 4, 16);
            const float* bp = Bb + (long)(k0 + b_r0) * ldb + bn0 + b_c0;
            cp16(b_dst0 + st * BST * 4, bp, b_sz);
            if (BN == 128) cp16(b_dst0 + st * BST * 4 + 8 * BLD * 4, bp + 8 * ldb, b_sz);
        }
        CP_COMMIT();
        buf = (buf + 1 < NST) ? buf + 1 : 0;
    }

#pragma unroll
    for (int mi = 0; mi < 2; mi++) {
        const int row0 = bm0 + wm0 + mi * 16 + lq;
#pragma unroll
        for (int ni = 0; ni < NI; ni++) {
            const int col = bn0 + wn0 + ni * 8 + 2 * lr;
            if (col < N) {
                float2 v0, v1;
                if (RC) {
                    v0 = make_float2(tf32f(acc[mi][ni][0]), tf32f(acc[mi][ni][1]));
                    v1 = make_float2(tf32f(acc[mi][ni][2]), tf32f(acc[mi][ni][3]));
                } else {
                    v0 = make_float2(acc[mi][ni][0], acc[mi][ni][1]);
                    v1 = make_float2(acc[mi][ni][2], acc[mi][ni][3]);
                }
                *(float2*)(Cb + (long)row0 * ldc + col)       = v0;
                *(float2*)(Cb + (long)(row0 + 8) * ldc + col) = v1;
            }
        }
    }
}

// ---------------- fused RMSNorm(768) + latent->k_in (both tf32-rounded) ----------------
__global__ void norm_fused_kernel(const float* __restrict__ qa, const float* __restrict__ g_qa,
                                  float* __restrict__ qan,
                                  const float* __restrict__ lat, const float* __restrict__ g_kva,
                                  const int* __restrict__ pos, float* __restrict__ kin)
{
    const int t   = blockIdx.x;
    const int tid = threadIdx.x;
    __shared__ float red[256];
    __shared__ float rinv_s;

    // ---- part 1: latent -> kin ----
    {
        const float* x = lat + (long)t * DQK;
        float v = x[tid];
        red[tid] = v * v;
        __syncthreads();
        for (int st = 128; st > 0; st >>= 1) { if (tid < st) red[tid] += red[tid + st]; __syncthreads(); }
        if (tid == 0) rinv_s = rsqrtf(red[0] / (float)KVLORA_ + EPS_);
        __syncthreads();
        kin[(long)t * DQK + tid] = tf32f(v * rinv_s * g_kva[tid]);
        if (tid < 16) {
            float p = (float)pos[t];
            float f = p * powf(10000.f, -(float)tid / 16.f);
            float c = cosf(f), s = sinf(f);
            float x1 = x[KVLORA_ + tid];
            float x2 = x[KVLORA_ + 16 + tid];
            kin[(long)t * DQK + KVLORA_ + tid]      = tf32f(x1 * c - x2 * s);
            kin[(long)t * DQK + KVLORA_ + 16 + tid] = tf32f(x2 * c + x1 * s);
        }
    }
    __syncthreads();

    // ---- part 2: rms768 ----
    {
        const float* x = qa + (long)t * QLORA_;
        float s = 0.f;
        for (int i = tid; i < QLORA_; i += 256) { float v = x[i]; s += v * v; }
        red[tid] = s;
        __syncthreads();
        for (int st = 128; st > 0; st >>= 1) { if (tid < st) red[tid] += red[tid + st]; __syncthreads(); }
        if (tid == 0) rinv_s = rsqrtf(red[0] / (float)QLORA_ + EPS_);
        __syncthreads();
        for (int i = tid; i < QLORA_; i += 256)
            qan[(long)t * QLORA_ + i] = tf32f(x[i] * rinv_s * g_qa[i]);
    }
}

// ---------------- RoPE q_pe ----------------
__global__ void rope_q_kernel(const float* __restrict__ q, const int* __restrict__ pos,
                              float* __restrict__ qin)
{
    int idx = blockIdx.x * blockDim.x + threadIdx.x;
    if (idx >= T_ * H_ * 16) return;
    int j = idx & 15;
    int h = (idx >> 4) % H_;
    int t = idx / (16 * H_);
    float p = (float)pos[t];
    float f = p * powf(10000.f, -(float)j / 16.f);
    float c = cosf(f), s = sinf(f);
    const float* qp = q + (long)t * (H_ * QHD) + h * QHD + NOPE_;
    float x1 = qp[j], x2 = qp[16 + j];
    float* o = qin + (long)t * (H_ * DQK) + h * DQK + KVLORA_;
    o[j]      = x1 * c - x2 * s;
    o[16 + j] = x2 * c + x1 * s;
}

// ---------------- flash attention v9: 3-buffer 32-row cp.async ring ----------------
#define KRLD 300
#define KHALF9 (32 * KRLD)
#define PLD4 68
#define QF_FLOATS (4 * 36 * 32 * 4)
#define ATTN9_SMEM ((QF_FLOATS + 3 * KHALF9 + 64 * PLD4 + 256 + 256 + 64 + 64) * 4)

#define ISSUE9(bb) do { \
    if ((bb) < nkb) { \
        const float* _src = kin + (size_t)((bb) * 32 + krow) * DQK + kc; \
        const unsigned _dst = kb_s + (unsigned)((((bb) % 3) * KHALF9 + krow * KRLD + kc) * 4); \
        _Pragma("unroll") \
        for (int _i = 0; _i < 9; _i++) cp16(_dst + _i * 16, _src + _i * 4, 16); \
    } \
    CP_COMMIT(); \
} while (0)

__global__ void __launch_bounds__(256, 1)
attn9_kernel(const float* __restrict__ qin, const float* __restrict__ kin,
             float* __restrict__ olat)
{
    extern __shared__ float sm[];
    float* Qf     = sm;                     // [4 mg][36 d8][32 lane][4 reg] tf32
    float* Kb     = Qf + QF_FLOATS;         // 3 x [32][KRLD] pre-rounded kin
    float* Ps     = Kb + 3 * KHALF9;        // [64][PLD4] tf32
    float* redmax = Ps + 64 * PLD4;         // [64][4]
    float* redsum = redmax + 256;
    float* m_s    = redsum + 256;
    float* l_s    = m_s + 64;

    const int h   = blockIdx.y;
    const int qb  = gridDim.x - 1 - blockIdx.x;   // heavy first
    const int i0  = qb * 64;
    const int tid = threadIdx.x;
    const int w    = tid >> 5;
    const int lane = tid & 31;
    const int wm   = (w & 1) * 32;
    const int wni  = w >> 1;              // 0..3
    const int wn   = wni * 8;             // S col base (within 32)
    const int wv   = wni * 64;            // O col base
    const int lq   = lane >> 2;
    const int lr   = lane & 3;
    const float scale = 0.102062072615966f;  // 1/sqrt(96)

    // ---- Q -> fragment-order smem (pre-scaled tf32) ----
    {
        const int row   = tid >> 2;
        const int dbase = (tid & 3) * 72;
        const int mg  = row >> 4;
        const int lq8 = row & 7;
        const int rb0 = (row >> 3) & 1;
        const float* src = qin + (size_t)(i0 + row) * (H_ * DQK) + h * DQK + dbase;
#pragma unroll
        for (int i = 0; i < 18; i++) {
            float4 v = *(const float4*)(src + i * 4);
            const int d0  = dbase + i * 4;
            const int d8  = d0 >> 3;
            const int reg = rb0 + ((d0 >> 2) & 1) * 2;
            float* dst = Qf + ((mg * 36 + d8) * 32 + lq8 * 4) * 4 + reg;
            dst[0]  = __uint_as_float(tf32c(v.x * scale));
            dst[4]  = __uint_as_float(tf32c(v.y * scale));
            dst[8]  = __uint_as_float(tf32c(v.z * scale));
            dst[12] = __uint_as_float(tf32c(v.w * scale));
        }
    }
    if (tid < 64) { m_s[tid] = -1e30f; l_s[tid] = 0.f; }

    float o[2][8][4];
#pragma unroll
    for (int mi = 0; mi < 2; mi++)
#pragma unroll
        for (int ni = 0; ni < 8; ni++)
#pragma unroll
            for (int r = 0; r < 4; r++) o[mi][ni][r] = 0.f;

    const unsigned kb_s = (unsigned)__cvta_generic_to_shared(Kb);
    const int krow = tid >> 3;            // 0..31
    const int kc   = (tid & 7) * 36;
    const int qmg0 = 2 * (w & 1);
    const int nkb  = 2 * qb + 2;          // 32-key blocks

    ISSUE9(0); ISSUE9(1);

    for (int kb = 0; kb < nkb; kb++) {
        CP_WAIT(1);          // retires through block kb (issued >=1 iteration ago)
        __syncthreads();     // all copies of block kb visible; buf[(kb+2)%3] free
        ISSUE9(kb + 2);

        const float* buf = Kb + (kb % 3) * KHALF9;
        const int j0 = kb * 32;

        // ---- S = Q K^T : 64 rows x 32 cols (warp: 32 rows x 8 cols) ----
        float s[2][4];
#pragma unroll
        for (int mi = 0; mi < 2; mi++)
#pragma unroll
            for (int r = 0; r < 4; r++) s[mi][r] = 0.f;

#pragma unroll 4
        for (int d8 = 0; d8 < 36; d8++) {
            unsigned a[2][4];
#pragma unroll
            for (int mi = 0; mi < 2; mi++) {
                float4 qv = *(const float4*)(Qf + (((qmg0 + mi) * 36 + d8) * 32 + lane) * 4);
                a[mi][0] = __float_as_uint(qv.x); a[mi][1] = __float_as_uint(qv.y);
                a[mi][2] = __float_as_uint(qv.z); a[mi][3] = __float_as_uint(qv.w);
            }
            const unsigned* kp = (const unsigned*)(buf + (wn + lq) * KRLD + d8 * 8 + lr);
            unsigned b0 = kp[0];
            unsigned b1 = kp[4];
            mma8(s[0], a[0], b0, b1);
            mma8(s[1], a[1], b0, b1);
        }

        // ---- causal mask (blocks overlapping diagonal) ----
        if (kb >= 2 * qb) {
#pragma unroll
            for (int mi = 0; mi < 2; mi++)
#pragma unroll
                for (int r = 0; r < 4; r++) {
                    int row = i0 + wm + 16 * mi + 8 * (r >> 1) + lq;
                    int col = j0 + wn + 2 * lr + (r & 1);
                    if (col > row) s[mi][r] = -1e30f;
                }
        }

        // ---- online softmax ----
#pragma unroll
        for (int mi = 0; mi < 2; mi++)
#pragma unroll
            for (int half = 0; half < 2; half++) {
                float mx = fmaxf(s[mi][2*half], s[mi][2*half+1]);
                mx = fmaxf(mx, __shfl_xor_sync(0xffffffffu, mx, 1));
                mx = fmaxf(mx, __shfl_xor_sync(0xffffffffu, mx, 2));
                if (lr == 0) redmax[(wm + 16 * mi + 8 * half + lq) * 4 + wni] = mx;
            }
        __syncthreads();

        float alpha[2][2], mnew[2][2];
#pragma unroll
        for (int mi = 0; mi < 2; mi++)
#pragma unroll
            for (int half = 0; half < 2; half++) {
                const int row = wm + 16 * mi + 8 * half + lq;
                const float* rp = redmax + row * 4;
                float bm = fmaxf(fmaxf(rp[0], rp[1]), fmaxf(rp[2], rp[3]));
                float mo = m_s[row];
                float mn = fmaxf(mo, bm);
                mnew[mi][half]  = mn;
                alpha[mi][half] = __expf(mo - mn);
                float p0 = __expf(s[mi][2*half]     - mn);
                float p1 = __expf(s[mi][2*half + 1] - mn);
                float su = p0 + p1;
                su += __shfl_xor_sync(0xffffffffu, su, 1);
                su += __shfl_xor_sync(0xffffffffu, su, 2);
                if (lr == 0) redsum[row * 4 + wni] = su;
                unsigned* pp = (unsigned*)(Ps + row * PLD4 + wn + 2 * lr);
                pp[0] = tf32c(p0);
                pp[1] = tf32c(p1);
            }
#pragma unroll
        for (int mi = 0; mi < 2; mi++)
#pragma unroll
            for (int ni = 0; ni < 8; ni++) {
                o[mi][ni][0] *= alpha[mi][0];
                o[mi][ni][1] *= alpha[mi][0];
                o[mi][ni][2] *= alpha[mi][1];
                o[mi][ni][3] *= alpha[mi][1];
            }
        __syncthreads();

        if (w < 2 && lr == 0) {
#pragma unroll
            for (int mi = 0; mi < 2; mi++)
#pragma unroll
                for (int half = 0; half < 2; half++) {
                    const int row = wm + 16 * mi + 8 * half + lq;
                    const float* rp = redsum + row * 4;
                    l_s[row] = l_s[row] * alpha[mi][half] + (rp[0] + rp[1] + rp[2] + rp[3]);
                    m_s[row] = mnew[mi][half];
                }
        }

        // ---- O += P @ V (V = buf cols 0..255, 32 rows -> kst 0..3) ----
#pragma unroll
        for (int kst = 0; kst < 4; kst++) {
            unsigned a[2][4];
#pragma unroll
            for (int mi = 0; mi < 2; mi++) {
                const unsigned* p0 = (const unsigned*)(Ps + (wm + 16 * mi + lq) * PLD4) + kst * 8 + lr;
                const unsigned* p1 = p0 + 8 * PLD4;
                a[mi][0] = p0[0]; a[mi][1] = p1[0]; a[mi][2] = p0[4]; a[mi][3] = p1[4];
            }
            const unsigned* vr0 = (const unsigned*)(buf + (kst * 8 + lr) * KRLD + wv + lq);
            const unsigned* vr1 = vr0 + 4 * KRLD;
#pragma unroll
            for (int ni = 0; ni < 8; ni++) {
                unsigned b0 = vr0[ni * 8];
                unsigned b1 = vr1[ni * 8];
                mma8(o[0][ni], a[0], b0, b1);
                mma8(o[1][ni], a[1], b0, b1);
            }
        }
    }

    CP_WAIT(0);
    __syncthreads();
#pragma unroll
    for (int mi = 0; mi < 2; mi++)
#pragma unroll
        for (int half = 0; half < 2; half++) {
            const int row = wm + 16 * mi + 8 * half + lq;
            const float linv = 1.f / l_s[row];
            float* dst = olat + (size_t)(i0 + row) * (H_ * KVLORA_) + h * KVLORA_;
#pragma unroll
            for (int ni = 0; ni < 8; ni++) {
                float2 v = make_float2(tf32f(o[mi][ni][2*half] * linv),
                                       tf32f(o[mi][ni][2*half + 1] * linv));
                *(float2*)(dst + wv + 8 * ni + 2 * lr) = v;
            }
        }
}

// ---------------- host ----------------
extern "C" void kernel_launch(void* const* d_in, const int* in_sizes, int n_in,
                              void* d_out, int out_size)
{
    const int*   positions = (const int*)  d_in[0];
    const float* hidden    = (const float*)d_in[1];
    const float* w_qa      = (const float*)d_in[2];
    const float* g_qa      = (const float*)d_in[3];
    const float* w_qb      = (const float*)d_in[4];
    const float* w_kva     = (const float*)d_in[5];
    const float* g_kva     = (const float*)d_in[6];
    const float* w_kc      = (const float*)d_in[7];
    const float* w_vc      = (const float*)d_in[8];
    const float* w_o       = (const float*)d_in[9];
    float* out = (float*)d_out;

    float *qa, *qan, *q, *lat, *kin, *qin, *olat, *ov;
    cudaGetSymbolAddress((void**)&qa,   sc_qa);
    cudaGetSymbolAddress((void**)&qan,  sc_qan);
    cudaGetSymbolAddress((void**)&q,    sc_q);
    cudaGetSymbolAddress((void**)&lat,  sc_lat);
    cudaGetSymbolAddress((void**)&kin,  sc_kin);
    cudaGetSymbolAddress((void**)&qin,  sc_qin);
    cudaGetSymbolAddress((void**)&olat, sc_olat);
    cudaGetSymbolAddress((void**)&ov,   sc_ov);

    cudaFuncSetAttribute(attn9_kernel, cudaFuncAttributeMaxDynamicSharedMemorySize, ATTN9_SMEM);
    cudaFuncSetAttribute((const void*)tgemm_ca<64,128,false,true>,   cudaFuncAttributeMaxDynamicSharedMemorySize, GEMM_SMEM(64,128));
    cudaFuncSetAttribute((const void*)tgemm_ca<128,128,true,false>,  cudaFuncAttributeMaxDynamicSharedMemorySize, GEMM_SMEM(128,128));
    cudaFuncSetAttribute((const void*)tgemm_ca<128,128,false,false>, cudaFuncAttributeMaxDynamicSharedMemorySize, GEMM_SMEM(128,128));
    cudaFuncSetAttribute((const void*)tgemm_ca<128,64,true,false>,   cudaFuncAttributeMaxDynamicSharedMemorySize, GEMM_SMEM(128,64));

    dim3 thr(256);

    // 1+4) DUAL: z=0 -> qa = hidden @ w_qa ; z=1 -> lat = hidden @ w_kva
    tgemm_ca<64,128,false,true><<<dim3(QLORA_/128, T_/64, 2), thr, GEMM_SMEM(64,128)>>>(
        hidden, w_qa, qa,
        T_, QLORA_, HID_, HID_, QLORA_, QLORA_, 0, 0, 0,
        w_kva, lat, DQK, DQK, DQK);
    // 2+5) fused rmsnorm + latent->kin
    norm_fused_kernel<<<T_, thr>>>(qa, g_qa, qan, lat, g_kva, positions, kin);
    // 3) q = qan @ w_qb (round C)
    tgemm_ca<128,128,true,false><<<dim3((H_*QHD)/128, T_/128, 1), thr, GEMM_SMEM(128,128)>>>(
        qan, w_qb, q,
        T_, H_*QHD, QLORA_, QLORA_, H_*QHD, H_*QHD, 0, 0, 0,
        nullptr, nullptr, 0, 0, 0);
    // 6) q_lat batched over heads
    tgemm_ca<128,128,false,false><<<dim3(KVLORA_/128, T_/128, H_), thr, GEMM_SMEM(128,128)>>>(
        q, w_kc, qin,
        T_, KVLORA_, NOPE_, H_*QHD, KVLORA_, H_*DQK,
        (long)QHD, (long)NOPE_*KVLORA_, (long)DQK,
        nullptr, nullptr, 0, 0, 0);
    // 7) rope q_pe
    rope_q_kernel<<<(T_*H_*16 + 255)/256, thr>>>(q, positions, qin);
    // 8) attention (3-buffer ring)
    attn9_kernel<<<dim3(T_/64, H_), thr, ATTN9_SMEM>>>(qin, kin, olat);
    // 9) v-proj batched
    tgemm_ca<128,64,true,false><<<dim3(1, T_/128, H_), thr, GEMM_SMEM(128,64)>>>(
        olat, w_vc, ov,
        T_, VDIM_, KVLORA_, H_*KVLORA_, VDIM_, H_*VDIM_,
        (long)KVLORA_, (long)KVLORA_*VDIM_, (long)VDIM_,
        nullptr, nullptr, 0, 0, 0);
    // 10) out = ov @ w_o
    tgemm_ca<128,128,false,false><<<dim3(HID_/128, T_/128, 1), thr, GEMM_SMEM(128,128)>>>(
        ov, w_o, out,
        T_, HID_, H_*VDIM_, H_*VDIM_, HID_, HID_, 0, 0, 0,
        nullptr, nullptr, 0, 0, 0);
}

// round 16
// speedup vs baseline: 1.2852x; 1.2852x over previous
#include <cuda_runtime.h>
#include <math.h>

#define T_      2048
#define HID_    2560
#define H_      40
#define NOPE_   64
#define ROPE_   32
#define VDIM_   64
#define QLORA_  768
#define KVLORA_ 256
#define DQK     288
#define QHD     96
#define EPS_    1e-5f

// ---------------- scratch ----------------
__device__ float sc_qa  [T_ * QLORA_];
__device__ float sc_qan [T_ * QLORA_];
__device__ float sc_q   [T_ * H_ * QHD];
__device__ float sc_lat [T_ * DQK];
__device__ float sc_kin [T_ * DQK];
__device__ float sc_qin [(size_t)T_ * H_ * DQK];
__device__ float sc_olat[(size_t)T_ * H_ * KVLORA_];
__device__ float sc_ov  [T_ * H_ * VDIM_];

// ---------------- tf32 / mma / cp.async helpers ----------------
__device__ __forceinline__ unsigned tf32c(float x) {
    unsigned u;
    asm("cvt.rna.tf32.f32 %0, %1;" : "=r"(u) : "f"(x));
    return u;
}
__device__ __forceinline__ float tf32f(float x) { return __uint_as_float(tf32c(x)); }
__device__ __forceinline__ void mma8(float c[4], const unsigned a[4], unsigned b0, unsigned b1) {
    asm volatile(
        "mma.sync.aligned.m16n8k8.row.col.f32.tf32.tf32.f32 "
        "{%0,%1,%2,%3},{%4,%5,%6,%7},{%8,%9},{%0,%1,%2,%3};\n"
        : "+f"(c[0]), "+f"(c[1]), "+f"(c[2]), "+f"(c[3])
        : "r"(a[0]), "r"(a[1]), "r"(a[2]), "r"(a[3]), "r"(b0), "r"(b1));
}
__device__ __forceinline__ void cp16(unsigned dst, const void* src, int sz) {
    asm volatile("cp.async.ca.shared.global [%0], [%1], 16, %2;\n"
                 :: "r"(dst), "l"(src), "r"(sz));
}
#define CP_COMMIT() asm volatile("cp.async.commit_group;\n" ::: "memory")
#define CP_WAIT(n)  asm volatile("cp.async.wait_group %0;\n" :: "n"(n) : "memory")

// ---------------- tf32 GEMM BMxBNx16, cp.async 4-stage pipeline ----------------
// DUAL mode: blockIdx.z==1 selects (B2, C2, N2) with same A; z-strides must be 0.
#define NST 4
#define ALD 20
#define GEMM_SMEM(BM,BN) ((NST * ((BM) * ALD) + NST * (16 * ((BN) == 128 ? 136 : 72))) * 4)

template<int BM, int BN, bool RC, bool DUAL>
__global__ void __launch_bounds__(256, 2)
tgemm_ca(const float* __restrict__ A, const float* __restrict__ B,
         float* __restrict__ C,
         int M, int N, int K, int lda, int ldb, int ldc,
         long sA, long sB, long sC,
         const float* __restrict__ B2, float* __restrict__ C2,
         int N2, int ldb2, int ldc2)
{
    constexpr int WARPS_M = BM / 32;
    constexpr int WN  = BN / (8 / WARPS_M);
    constexpr int NI  = WN / 8;
    constexpr int BLD = (BN == 128) ? 136 : 72;
    constexpr int AST = BM * ALD;
    constexpr int BST = 16 * BLD;
    extern __shared__ float smem[];
    float* Asm = smem;
    float* Bsm = smem + NST * AST;

    const int bm0 = blockIdx.y * BM;
    const int bn0 = blockIdx.x * BN;

    const float* Ab;
    const float* Bb;
    float*       Cb;
    if (DUAL && blockIdx.z == 1) {
        if (bn0 >= N2) return;
        Ab = A; Bb = B2; Cb = C2;
        N = N2; ldb = ldb2; ldc = ldc2;
    } else {
        Ab = A + (long)blockIdx.z * sA;
        Bb = B + (long)blockIdx.z * sB;
        Cb = C + (long)blockIdx.z * sC;
    }

    const int tid = threadIdx.x;
    const int w    = tid >> 5;
    const int lane = tid & 31;
    const int lq   = lane >> 2;
    const int lr   = lane & 3;
    const int wm0  = (w % WARPS_M) * 32;
    const int wn0  = (w / WARPS_M) * WN;

    const int a_row = (BM == 128) ? (tid >> 1) : (tid >> 2);
    const int a_k0  = (BM == 128) ? (tid & 1) * 8 : (tid & 3) * 4;
    const int b_r0  = (BN == 128) ? (tid >> 5) : (tid >> 4);
    const int b_c0  = (BN == 128) ? (tid & 31) * 4 : (tid & 15) * 4;
    const int b_sz  = (bn0 + b_c0 < N) ? 16 : 0;

    const unsigned a_dst0 = (unsigned)__cvta_generic_to_shared(Asm) + (a_row * ALD + a_k0) * 4;
    const unsigned b_dst0 = (unsigned)__cvta_generic_to_shared(Bsm) + (b_r0 * BLD + b_c0) * 4;

    float acc[2][NI][4];
#pragma unroll
    for (int mi = 0; mi < 2; mi++)
#pragma unroll
        for (int ni = 0; ni < NI; ni++)
#pragma unroll
            for (int r = 0; r < 4; r++) acc[mi][ni][r] = 0.f;

    const int nc = K / 16;

#pragma unroll
    for (int s = 0; s < NST - 1; s++) {
        if (s < nc) {
            const int k0 = s * 16;
            const float* ap = Ab + (long)(bm0 + a_row) * lda + k0 + a_k0;
            cp16(a_dst0 + s * AST * 4, ap, 16);
            if (BM == 128) cp16(a_dst0 + s * AST * 4 + 16, ap + 4, 16);
            const float* bp = Bb + (long)(k0 + b_r0) * ldb + bn0 + b_c0;
            cp16(b_dst0 + s * BST * 4, bp, b_sz);
            if (BN == 128) cp16(b_dst0 + s * BST * 4 + 8 * BLD * 4, bp + 8 * ldb, b_sz);
        }
        CP_COMMIT();
    }

    int buf = 0;
    for (int c = 0; c < nc; c++) {
        CP_WAIT(NST - 2);
        __syncthreads();

        const float* Ab_s = Asm + buf * AST;
        const float* Bb_s = Bsm + buf * BST;
#pragma unroll
        for (int ks = 0; ks < 2; ks++) {
            const int kb = ks * 8;
            unsigned afr[2][4];
#pragma unroll
            for (int mi = 0; mi < 2; mi++) {
                const float* r0 = Ab_s + (wm0 + 16 * mi + lq) * ALD + kb + lr;
                afr[mi][0] = tf32c(r0[0]);
                afr[mi][1] = tf32c(r0[8 * ALD]);
                afr[mi][2] = tf32c(r0[4]);
                afr[mi][3] = tf32c(r0[8 * ALD + 4]);
            }
            const float* brow0 = Bb_s + (kb + lr) * BLD + wn0 + lq;
            const float* brow1 = brow0 + 4 * BLD;
#pragma unroll
            for (int ni = 0; ni < NI; ni++) {
                unsigned b0 = tf32c(brow0[ni * 8]);
                unsigned b1 = tf32c(brow1[ni * 8]);
                mma8(acc[0][ni], afr[0], b0, b1);
                mma8(acc[1][ni], afr[1], b0, b1);
            }
        }

        const int cs = c + NST - 1;
        if (cs < nc) {
            const int st = cs % NST;
            const int k0 = cs * 16;
            const float* ap = Ab + (long)(bm0 + a_row) * lda + k0 + a_k0;
            cp16(a_dst0 + st * AST * 4, ap, 16);
            if (BM == 128) cp16(a_dst0 + st * AST * 4 + 16, ap + 4, 16);
            const float* bp = Bb + (long)(k0 + b_r0) * ldb + bn0 + b_c0;
            cp16(b_dst0 + st * BST * 4, bp, b_sz);
            if (BN == 128) cp16(b_dst0 + st * BST * 4 + 8 * BLD * 4, bp + 8 * ldb, b_sz);
        }
        CP_COMMIT();
        buf = (buf + 1 < NST) ? buf + 1 : 0;
    }

#pragma unroll
    for (int mi = 0; mi < 2; mi++) {
        const int row0 = bm0 + wm0 + mi * 16 + lq;
#pragma unroll
        for (int ni = 0; ni < NI; ni++) {
            const int col = bn0 + wn0 + ni * 8 + 2 * lr;
            if (col < N) {
                float2 v0, v1;
                if (RC) {
                    v0 = make_float2(tf32f(acc[mi][ni][0]), tf32f(acc[mi][ni][1]));
                    v1 = make_float2(tf32f(acc[mi][ni][2]), tf32f(acc[mi][ni][3]));
                } else {
                    v0 = make_float2(acc[mi][ni][0], acc[mi][ni][1]);
                    v1 = make_float2(acc[mi][ni][2], acc[mi][ni][3]);
                }
                *(float2*)(Cb + (long)row0 * ldc + col)       = v0;
                *(float2*)(Cb + (long)(row0 + 8) * ldc + col) = v1;
            }
        }
    }
}

// ---------------- fused RMSNorm(768) + latent->k_in (both tf32-rounded) ----------------
__global__ void norm_fused_kernel(const float* __restrict__ qa, const float* __restrict__ g_qa,
                                  float* __restrict__ qan,
                                  const float* __restrict__ lat, const float* __restrict__ g_kva,
                                  const int* __restrict__ pos, float* __restrict__ kin)
{
    const int t   = blockIdx.x;
    const int tid = threadIdx.x;
    __shared__ float red[256];
    __shared__ float rinv_s;

    // ---- part 1: latent -> kin ----
    {
        const float* x = lat + (long)t * DQK;
        float v = x[tid];
        red[tid] = v * v;
        __syncthreads();
        for (int st = 128; st > 0; st >>= 1) { if (tid < st) red[tid] += red[tid + st]; __syncthreads(); }
        if (tid == 0) rinv_s = rsqrtf(red[0] / (float)KVLORA_ + EPS_);
        __syncthreads();
        kin[(long)t * DQK + tid] = tf32f(v * rinv_s * g_kva[tid]);
        if (tid < 16) {
            float p = (float)pos[t];
            float f = p * powf(10000.f, -(float)tid / 16.f);
            float c = cosf(f), s = sinf(f);
            float x1 = x[KVLORA_ + tid];
            float x2 = x[KVLORA_ + 16 + tid];
            kin[(long)t * DQK + KVLORA_ + tid]      = tf32f(x1 * c - x2 * s);
            kin[(long)t * DQK + KVLORA_ + 16 + tid] = tf32f(x2 * c + x1 * s);
        }
    }
    __syncthreads();

    // ---- part 2: rms768 ----
    {
        const float* x = qa + (long)t * QLORA_;
        float s = 0.f;
        for (int i = tid; i < QLORA_; i += 256) { float v = x[i]; s += v * v; }
        red[tid] = s;
        __syncthreads();
        for (int st = 128; st > 0; st >>= 1) { if (tid < st) red[tid] += red[tid + st]; __syncthreads(); }
        if (tid == 0) rinv_s = rsqrtf(red[0] / (float)QLORA_ + EPS_);
        __syncthreads();
        for (int i = tid; i < QLORA_; i += 256)
            qan[(long)t * QLORA_ + i] = tf32f(x[i] * rinv_s * g_qa[i]);
    }
}

// ---------------- RoPE q_pe ----------------
__global__ void rope_q_kernel(const float* __restrict__ q, const int* __restrict__ pos,
                              float* __restrict__ qin)
{
    int idx = blockIdx.x * blockDim.x + threadIdx.x;
    if (idx >= T_ * H_ * 16) return;
    int j = idx & 15;
    int h = (idx >> 4) % H_;
    int t = idx / (16 * H_);
    float p = (float)pos[t];
    float f = p * powf(10000.f, -(float)j / 16.f);
    float c = cosf(f), s = sinf(f);
    const float* qp = q + (long)t * (H_ * QHD) + h * QHD + NOPE_;
    float x1 = qp[j], x2 = qp[16 + j];
    float* o = qin + (long)t * (H_ * DQK) + h * DQK + KVLORA_;
    o[j]      = x1 * c - x2 * s;
    o[16 + j] = x2 * c + x1 * s;
}

// ---------------- flash attention v8b: split-half wait + KRLD=300 ----------------
#define KRLD 300
#define PLD4 68
#define QF_FLOATS (4 * 36 * 32 * 4)
#define ATTN8_SMEM ((QF_FLOATS + 64 * KRLD + 64 * PLD4 + 256 + 256 + 64 + 64) * 4)

__global__ void __launch_bounds__(256, 1)
attn8_kernel(const float* __restrict__ qin, const float* __restrict__ kin,
             float* __restrict__ olat)
{
    extern __shared__ float sm[];
    float* Qf     = sm;
    float* Kraw   = Qf + QF_FLOATS;
    float* Ps     = Kraw + 64 * KRLD;
    float* redmax = Ps + 64 * PLD4;
    float* redsum = redmax + 256;
    float* m_s    = redsum + 256;
    float* l_s    = m_s + 64;

    const int h   = blockIdx.y;
    const int qb  = gridDim.x - 1 - blockIdx.x;
    const int i0  = qb * 64;
    const int tid = threadIdx.x;
    const int w    = tid >> 5;
    const int lane = tid & 31;
    const int wm   = (w & 1) * 32;
    const int wni  = w >> 1;
    const int wn   = wni * 16;
    const int wv   = wni * 64;
    const int lq   = lane >> 2;
    const int lr   = lane & 3;
    const float scale = 0.102062072615966f;  // 1/sqrt(96)

    // ---- Q -> fragment-order smem (pre-scaled tf32) ----
    {
        const int row   = tid >> 2;
        const int dbase = (tid & 3) * 72;
        const int mg  = row >> 4;
        const int lq8 = row & 7;
        const int rb0 = (row >> 3) & 1;
        const float* src = qin + (size_t)(i0 + row) * (H_ * DQK) + h * DQK + dbase;
#pragma unroll
        for (int i = 0; i < 18; i++) {
            float4 v = *(const float4*)(src + i * 4);
            const int d0  = dbase + i * 4;
            const int d8  = d0 >> 3;
            const int reg = rb0 + ((d0 >> 2) & 1) * 2;
            float* dst = Qf + ((mg * 36 + d8) * 32 + lq8 * 4) * 4 + reg;
            dst[0]  = __uint_as_float(tf32c(v.x * scale));
            dst[4]  = __uint_as_float(tf32c(v.y * scale));
            dst[8]  = __uint_as_float(tf32c(v.z * scale));
            dst[12] = __uint_as_float(tf32c(v.w * scale));
        }
    }
    if (tid < 64) { m_s[tid] = -1e30f; l_s[tid] = 0.f; }

    float o[2][8][4];
#pragma unroll
    for (int mi = 0; mi < 2; mi++)
#pragma unroll
        for (int ni = 0; ni < 8; ni++)
#pragma unroll
            for (int r = 0; r < 4; r++) o[mi][ni][r] = 0.f;

    const unsigned kraw_s = (unsigned)__cvta_generic_to_shared(Kraw);
    const int wg    = tid >> 7;
    const int lrow  = ((tid & 127) >> 2) + wg * 32;
    const int lcol  = (tid & 3) * 72;
    const int qmg0  = 2 * (w & 1);
    const int nkb   = qb + 1;

    for (int kb = 0; kb < nkb; kb++) {
        const int j0 = kb * 64;
        __syncthreads();

        {
            const float* src = kin + (size_t)(j0 + lrow) * DQK + lcol;
            const unsigned dst = kraw_s + (unsigned)(lrow * KRLD + lcol) * 4;
#pragma unroll
            for (int i = 0; i < 18; i++)
                cp16(dst + i * 16, src + i * 4, 16);
        }
        CP_COMMIT();
        CP_WAIT(0);
        if (wg == 0) asm volatile("bar.sync 1, 128;" ::: "memory");
        else         asm volatile("bar.sync 2, 128;" ::: "memory");

        if (kb + 1 < nkb) {
            const float* p = kin + (size_t)(j0 + 64 + lrow) * DQK + lcol;
            asm volatile("prefetch.global.L2 [%0];" :: "l"(p));
            asm volatile("prefetch.global.L2 [%0];" :: "l"(p + 36));
        }

        float s[2][2][4];
#pragma unroll
        for (int mi = 0; mi < 2; mi++)
#pragma unroll
            for (int ni = 0; ni < 2; ni++)
#pragma unroll
                for (int r = 0; r < 4; r++) s[mi][ni][r] = 0.f;

#pragma unroll 4
        for (int d8 = 0; d8 < 36; d8++) {
            unsigned a[2][4];
#pragma unroll
            for (int mi = 0; mi < 2; mi++) {
                float4 qv = *(const float4*)(Qf + (((qmg0 + mi) * 36 + d8) * 32 + lane) * 4);
                a[mi][0] = __float_as_uint(qv.x); a[mi][1] = __float_as_uint(qv.y);
                a[mi][2] = __float_as_uint(qv.z); a[mi][3] = __float_as_uint(qv.w);
            }
#pragma unroll
            for (int ni = 0; ni < 2; ni++) {
                const unsigned* kp = (const unsigned*)(Kraw + (wn + 8 * ni + lq) * KRLD + d8 * 8 + lr);
                unsigned b0 = kp[0];
                unsigned b1 = kp[4];
                mma8(s[0][ni], a[0], b0, b1);
                mma8(s[1][ni], a[1], b0, b1);
            }
        }

        if (kb == qb) {
#pragma unroll
            for (int mi = 0; mi < 2; mi++)
#pragma unroll
                for (int ni = 0; ni < 2; ni++)
#pragma unroll
                    for (int r = 0; r < 4; r++) {
                        int row = wm + 16 * mi + 8 * (r >> 1) + lq;
                        int col = wn + 8 * ni + 2 * lr + (r & 1);
                        if (col > row) s[mi][ni][r] = -1e30f;
                    }
        }

#pragma unroll
        for (int mi = 0; mi < 2; mi++)
#pragma unroll
            for (int half = 0; half < 2; half++) {
                float mx = fmaxf(fmaxf(s[mi][0][2*half], s[mi][0][2*half+1]),
                                 fmaxf(s[mi][1][2*half], s[mi][1][2*half+1]));
                mx = fmaxf(mx, __shfl_xor_sync(0xffffffffu, mx, 1));
                mx = fmaxf(mx, __shfl_xor_sync(0xffffffffu, mx, 2));
                if (lr == 0) redmax[(wm + 16 * mi + 8 * half + lq) * 4 + wni] = mx;
            }
        __syncthreads();

        float alpha[2][2], mnew[2][2];
#pragma unroll
        for (int mi = 0; mi < 2; mi++)
#pragma unroll
            for (int half = 0; half < 2; half++) {
                const int row = wm + 16 * mi + 8 * half + lq;
                const float* rp = redmax + row * 4;
                float bm = fmaxf(fmaxf(rp[0], rp[1]), fmaxf(rp[2], rp[3]));
                float mo = m_s[row];
                float mn = fmaxf(mo, bm);
                mnew[mi][half]  = mn;
                alpha[mi][half] = __expf(mo - mn);
                float p0[2], p1[2];
#pragma unroll
                for (int ni = 0; ni < 2; ni++) {
                    p0[ni] = __expf(s[mi][ni][2*half]     - mn);
                    p1[ni] = __expf(s[mi][ni][2*half + 1] - mn);
                }
                float su = p0[0] + p1[0] + p0[1] + p1[1];
                su += __shfl_xor_sync(0xffffffffu, su, 1);
                su += __shfl_xor_sync(0xffffffffu, su, 2);
                if (lr == 0) redsum[row * 4 + wni] = su;
#pragma unroll
                for (int ni = 0; ni < 2; ni++) {
                    unsigned* pp = (unsigned*)(Ps + row * PLD4 + wn + 8 * ni + 2 * lr);
                    pp[0] = tf32c(p0[ni]);
                    pp[1] = tf32c(p1[ni]);
                }
            }
#pragma unroll
        for (int mi = 0; mi < 2; mi++)
#pragma unroll
            for (int ni = 0; ni < 8; ni++) {
                o[mi][ni][0] *= alpha[mi][0];
                o[mi][ni][1] *= alpha[mi][0];
                o[mi][ni][2] *= alpha[mi][1];
                o[mi][ni][3] *= alpha[mi][1];
            }
        __syncthreads();

        if (w < 2 && lr == 0) {
#pragma unroll
            for (int mi = 0; mi < 2; mi++)
#pragma unroll
                for (int half = 0; half < 2; half++) {
                    const int row = wm + 16 * mi + 8 * half + lq;
                    const float* rp = redsum + row * 4;
                    l_s[row] = l_s[row] * alpha[mi][half] + (rp[0] + rp[1] + rp[2] + rp[3]);
                    m_s[row] = mnew[mi][half];
                }
        }

#pragma unroll
        for (int kst = 0; kst < 8; kst++) {
            unsigned a[2][4];
#pragma unroll
            for (int mi = 0; mi < 2; mi++) {
                const unsigned* p0 = (const unsigned*)(Ps + (wm + 16 * mi + lq) * PLD4) + kst * 8 + lr;
                const unsigned* p1 = p0 + 8 * PLD4;
                a[mi][0] = p0[0]; a[mi][1] = p1[0]; a[mi][2] = p0[4]; a[mi][3] = p1[4];
            }
            const unsigned* vr0 = (const unsigned*)(Kraw + (kst * 8 + lr) * KRLD + wv + lq);
            const unsigned* vr1 = vr0 + 4 * KRLD;
#pragma unroll
            for (int ni = 0; ni < 8; ni++) {
                unsigned b0 = vr0[ni * 8];
                unsigned b1 = vr1[ni * 8];
                mma8(o[0][ni], a[0], b0, b1);
                mma8(o[1][ni], a[1], b0, b1);
            }
        }
    }

    __syncthreads();
#pragma unroll
    for (int mi = 0; mi < 2; mi++)
#pragma unroll
        for (int half = 0; half < 2; half++) {
            const int row = wm + 16 * mi + 8 * half + lq;
            const float linv = 1.f / l_s[row];
            float* dst = olat + (size_t)(i0 + row) * (H_ * KVLORA_) + h * KVLORA_;
#pragma unroll
            for (int ni = 0; ni < 8; ni++) {
                float2 v = make_float2(tf32f(o[mi][ni][2*half] * linv),
                                       tf32f(o[mi][ni][2*half + 1] * linv));
                *(float2*)(dst + wv + 8 * ni + 2 * lr) = v;
            }
        }
}

// ---------------- host ----------------
extern "C" void kernel_launch(void* const* d_in, const int* in_sizes, int n_in,
                              void* d_out, int out_size)
{
    const int*   positions = (const int*)  d_in[0];
    const float* hidden    = (const float*)d_in[1];
    const float* w_qa      = (const float*)d_in[2];
    const float* g_qa      = (const float*)d_in[3];
    const float* w_qb      = (const float*)d_in[4];
    const float* w_kva     = (const float*)d_in[5];
    const float* g_kva     = (const float*)d_in[6];
    const float* w_kc      = (const float*)d_in[7];
    const float* w_vc      = (const float*)d_in[8];
    const float* w_o       = (const float*)d_in[9];
    float* out = (float*)d_out;

    float *qa, *qan, *q, *lat, *kin, *qin, *olat, *ov;
    cudaGetSymbolAddress((void**)&qa,   sc_qa);
    cudaGetSymbolAddress((void**)&qan,  sc_qan);
    cudaGetSymbolAddress((void**)&q,    sc_q);
    cudaGetSymbolAddress((void**)&lat,  sc_lat);
    cudaGetSymbolAddress((void**)&kin,  sc_kin);
    cudaGetSymbolAddress((void**)&qin,  sc_qin);
    cudaGetSymbolAddress((void**)&olat, sc_olat);
    cudaGetSymbolAddress((void**)&ov,   sc_ov);

    cudaFuncSetAttribute(attn8_kernel, cudaFuncAttributeMaxDynamicSharedMemorySize, ATTN8_SMEM);
    cudaFuncSetAttribute((const void*)tgemm_ca<64,128,false,true>,   cudaFuncAttributeMaxDynamicSharedMemorySize, GEMM_SMEM(64,128));
    cudaFuncSetAttribute((const void*)tgemm_ca<128,128,true,false>,  cudaFuncAttributeMaxDynamicSharedMemorySize, GEMM_SMEM(128,128));
    cudaFuncSetAttribute((const void*)tgemm_ca<128,128,false,false>, cudaFuncAttributeMaxDynamicSharedMemorySize, GEMM_SMEM(128,128));
    cudaFuncSetAttribute((const void*)tgemm_ca<128,64,true,false>,   cudaFuncAttributeMaxDynamicSharedMemorySize, GEMM_SMEM(128,64));

    dim3 thr(256);

    // 1+4) DUAL: z=0 -> qa = hidden @ w_qa ; z=1 -> lat = hidden @ w_kva
    tgemm_ca<64,128,false,true><<<dim3(QLORA_/128, T_/64, 2), thr, GEMM_SMEM(64,128)>>>(
        hidden, w_qa, qa,
        T_, QLORA_, HID_, HID_, QLORA_, QLORA_, 0, 0, 0,
        w_kva, lat, DQK, DQK, DQK);
    // 2+5) fused rmsnorm + latent->kin
    norm_fused_kernel<<<T_, thr>>>(qa, g_qa, qan, lat, g_kva, positions, kin);
    // 3) q = qan @ w_qb (round C)
    tgemm_ca<128,128,true,false><<<dim3((H_*QHD)/128, T_/128, 1), thr, GEMM_SMEM(128,128)>>>(
        qan, w_qb, q,
        T_, H_*QHD, QLORA_, QLORA_, H_*QHD, H_*QHD, 0, 0, 0,
        nullptr, nullptr, 0, 0, 0);
    // 6) q_lat batched over heads
    tgemm_ca<128,128,false,false><<<dim3(KVLORA_/128, T_/128, H_), thr, GEMM_SMEM(128,128)>>>(
        q, w_kc, qin,
        T_, KVLORA_, NOPE_, H_*QHD, KVLORA_, H_*DQK,
        (long)QHD, (long)NOPE_*KVLORA_, (long)DQK,
        nullptr, nullptr, 0, 0, 0);
    // 7) rope q_pe
    rope_q_kernel<<<(T_*H_*16 + 255)/256, thr>>>(q, positions, qin);
    // 8) attention (attn8: best-known)
    attn8_kernel<<<dim3(T_/64, H_), thr, ATTN8_SMEM>>>(qin, kin, olat);
    // 9) v-proj batched
    tgemm_ca<128,64,true,false><<<dim3(1, T_/128, H_), thr, GEMM_SMEM(128,64)>>>(
        olat, w_vc, ov,
        T_, VDIM_, KVLORA_, H_*KVLORA_, VDIM_, H_*VDIM_,
        (long)KVLORA_, (long)KVLORA_*VDIM_, (long)VDIM_,
        nullptr, nullptr, 0, 0, 0);
    // 10) out = ov @ w_o
    tgemm_ca<128,128,false,false><<<dim3(HID_/128, T_/128, 1), thr, GEMM_SMEM(128,128)>>>(
        ov, w_o, out,
        T_, HID_, H_*VDIM_, H_*VDIM_, HID_, HID_, 0, 0, 0,
        nullptr, nullptr, 0, 0, 0);
}

// round 17
// speedup vs baseline: 1.3271x; 1.0326x over previous
#include <cuda_runtime.h>
#include <math.h>

#define T_      2048
#define HID_    2560
#define H_      40
#define NOPE_   64
#define ROPE_   32
#define VDIM_   64
#define QLORA_  768
#define KVLORA_ 256
#define DQK     288
#define QHD     96
#define EPS_    1e-5f

// ---------------- scratch ----------------
__device__ float sc_qa  [T_ * QLORA_];
__device__ float sc_qan [T_ * QLORA_];
__device__ float sc_q   [T_ * H_ * QHD];
__device__ float sc_lat [T_ * DQK];
__device__ float sc_kin [T_ * DQK];
__device__ float sc_qin [(size_t)T_ * H_ * DQK];
__device__ float sc_olat[(size_t)T_ * H_ * KVLORA_];
__device__ float sc_ov  [T_ * H_ * VDIM_];

// ---------------- tf32 / mma / cp.async helpers ----------------
__device__ __forceinline__ unsigned tf32c(float x) {
    unsigned u;
    asm("cvt.rna.tf32.f32 %0, %1;" : "=r"(u) : "f"(x));
    return u;
}
__device__ __forceinline__ float tf32f(float x) { return __uint_as_float(tf32c(x)); }
__device__ __forceinline__ void mma8(float c[4], const unsigned a[4], unsigned b0, unsigned b1) {
    asm volatile(
        "mma.sync.aligned.m16n8k8.row.col.f32.tf32.tf32.f32 "
        "{%0,%1,%2,%3},{%4,%5,%6,%7},{%8,%9},{%0,%1,%2,%3};\n"
        : "+f"(c[0]), "+f"(c[1]), "+f"(c[2]), "+f"(c[3])
        : "r"(a[0]), "r"(a[1]), "r"(a[2]), "r"(a[3]), "r"(b0), "r"(b1));
}
__device__ __forceinline__ void cp16(unsigned dst, const void* src, int sz) {
    asm volatile("cp.async.ca.shared.global [%0], [%1], 16, %2;\n"
                 :: "r"(dst), "l"(src), "r"(sz));
}
#define CP_COMMIT() asm volatile("cp.async.commit_group;\n" ::: "memory")
#define CP_WAIT(n)  asm volatile("cp.async.wait_group %0;\n" :: "n"(n) : "memory")

// ---------------- tf32 GEMM BMxBNx16, cp.async 4-stage pipeline ----------------
// DUAL mode: blockIdx.z==1 selects (B2, C2, N2) with same A; z-strides must be 0.
#define NST 4
#define ALD 20
#define GEMM_SMEM(BM,BN) ((NST * ((BM) * ALD) + NST * (16 * ((BN) == 128 ? 136 : 72))) * 4)

template<int BM, int BN, bool RC, bool DUAL>
__global__ void __launch_bounds__(256, 2)
tgemm_ca(const float* __restrict__ A, const float* __restrict__ B,
         float* __restrict__ C,
         int M, int N, int K, int lda, int ldb, int ldc,
         long sA, long sB, long sC,
         const float* __restrict__ B2, float* __restrict__ C2,
         int N2, int ldb2, int ldc2)
{
    constexpr int WARPS_M = BM / 32;
    constexpr int WN  = BN / (8 / WARPS_M);
    constexpr int NI  = WN / 8;
    constexpr int BLD = (BN == 128) ? 136 : 72;
    constexpr int AST = BM * ALD;
    constexpr int BST = 16 * BLD;
    extern __shared__ float smem[];
    float* Asm = smem;
    float* Bsm = smem + NST * AST;

    const int bm0 = blockIdx.y * BM;
    const int bn0 = blockIdx.x * BN;

    const float* Ab;
    const float* Bb;
    float*       Cb;
    if (DUAL && blockIdx.z == 1) {
        if (bn0 >= N2) return;
        Ab = A; Bb = B2; Cb = C2;
        N = N2; ldb = ldb2; ldc = ldc2;
    } else {
        Ab = A + (long)blockIdx.z * sA;
        Bb = B + (long)blockIdx.z * sB;
        Cb = C + (long)blockIdx.z * sC;
    }

    const int tid = threadIdx.x;
    const int w    = tid >> 5;
    const int lane = tid & 31;
    const int lq   = lane >> 2;
    const int lr   = lane & 3;
    const int wm0  = (w % WARPS_M) * 32;
    const int wn0  = (w / WARPS_M) * WN;

    const int a_row = (BM == 128) ? (tid >> 1) : (tid >> 2);
    const int a_k0  = (BM == 128) ? (tid & 1) * 8 : (tid & 3) * 4;
    const int b_r0  = (BN == 128) ? (tid >> 5) : (tid >> 4);
    const int b_c0  = (BN == 128) ? (tid & 31) * 4 : (tid & 15) * 4;
    const int b_sz  = (bn0 + b_c0 < N) ? 16 : 0;

    const unsigned a_dst0 = (unsigned)__cvta_generic_to_shared(Asm) + (a_row * ALD + a_k0) * 4;
    const unsigned b_dst0 = (unsigned)__cvta_generic_to_shared(Bsm) + (b_r0 * BLD + b_c0) * 4;

    float acc[2][NI][4];
#pragma unroll
    for (int mi = 0; mi < 2; mi++)
#pragma unroll
        for (int ni = 0; ni < NI; ni++)
#pragma unroll
            for (int r = 0; r < 4; r++) acc[mi][ni][r] = 0.f;

    const int nc = K / 16;

#pragma unroll
    for (int s = 0; s < NST - 1; s++) {
        if (s < nc) {
            const int k0 = s * 16;
            const float* ap = Ab + (long)(bm0 + a_row) * lda + k0 + a_k0;
            cp16(a_dst0 + s * AST * 4, ap, 16);
            if (BM == 128) cp16(a_dst0 + s * AST * 4 + 16, ap + 4, 16);
            const float* bp = Bb + (long)(k0 + b_r0) * ldb + bn0 + b_c0;
            cp16(b_dst0 + s * BST * 4, bp, b_sz);
            if (BN == 128) cp16(b_dst0 + s * BST * 4 + 8 * BLD * 4, bp + 8 * ldb, b_sz);
        }
        CP_COMMIT();
    }

    int buf = 0;
    for (int c = 0; c < nc; c++) {
        CP_WAIT(NST - 2);
        __syncthreads();

        const float* Ab_s = Asm + buf * AST;
        const float* Bb_s = Bsm + buf * BST;
#pragma unroll
        for (int ks = 0; ks < 2; ks++) {
            const int kb = ks * 8;
            unsigned afr[2][4];
#pragma unroll
            for (int mi = 0; mi < 2; mi++) {
                const float* r0 = Ab_s + (wm0 + 16 * mi + lq) * ALD + kb + lr;
                afr[mi][0] = tf32c(r0[0]);
                afr[mi][1] = tf32c(r0[8 * ALD]);
                afr[mi][2] = tf32c(r0[4]);
                afr[mi][3] = tf32c(r0[8 * ALD + 4]);
            }
            const float* brow0 = Bb_s + (kb + lr) * BLD + wn0 + lq;
            const float* brow1 = brow0 + 4 * BLD;
#pragma unroll
            for (int ni = 0; ni < NI; ni++) {
                unsigned b0 = tf32c(brow0[ni * 8]);
                unsigned b1 = tf32c(brow1[ni * 8]);
                mma8(acc[0][ni], afr[0], b0, b1);
                mma8(acc[1][ni], afr[1], b0, b1);
            }
        }

        const int cs = c + NST - 1;
        if (cs < nc) {
            const int st = cs % NST;
            const int k0 = cs * 16;
            const float* ap = Ab + (long)(bm0 + a_row) * lda + k0 + a_k0;
            cp16(a_dst0 + st * AST * 4, ap, 16);
            if (BM == 128) cp16(a_dst0 + st * AST * 4 + 16, ap + 4, 16);
            const float* bp = Bb + (long)(k0 + b_r0) * ldb + bn0 + b_c0;
            cp16(b_dst0 + st * BST * 4, bp, b_sz);
            if (BN == 128) cp16(b_dst0 + st * BST * 4 + 8 * BLD * 4, bp + 8 * ldb, b_sz);
        }
        CP_COMMIT();
        buf = (buf + 1 < NST) ? buf + 1 : 0;
    }

#pragma unroll
    for (int mi = 0; mi < 2; mi++) {
        const int row0 = bm0 + wm0 + mi * 16 + lq;
#pragma unroll
        for (int ni = 0; ni < NI; ni++) {
            const int col = bn0 + wn0 + ni * 8 + 2 * lr;
            if (col < N) {
                float2 v0, v1;
                if (RC) {
                    v0 = make_float2(tf32f(acc[mi][ni][0]), tf32f(acc[mi][ni][1]));
                    v1 = make_float2(tf32f(acc[mi][ni][2]), tf32f(acc[mi][ni][3]));
                } else {
                    v0 = make_float2(acc[mi][ni][0], acc[mi][ni][1]);
                    v1 = make_float2(acc[mi][ni][2], acc[mi][ni][3]);
                }
                *(float2*)(Cb + (long)row0 * ldc + col)       = v0;
                *(float2*)(Cb + (long)(row0 + 8) * ldc + col) = v1;
            }
        }
    }
}

// ---------------- fused RMSNorm(768) + latent->k_in (both tf32-rounded) ----------------
__global__ void norm_fused_kernel(const float* __restrict__ qa, const float* __restrict__ g_qa,
                                  float* __restrict__ qan,
                                  const float* __restrict__ lat, const float* __restrict__ g_kva,
                                  const int* __restrict__ pos, float* __restrict__ kin)
{
    const int t   = blockIdx.x;
    const int tid = threadIdx.x;
    __shared__ float red[256];
    __shared__ float rinv_s;

    // ---- part 1: latent -> kin ----
    {
        const float* x = lat + (long)t * DQK;
        float v = x[tid];
        red[tid] = v * v;
        __syncthreads();
        for (int st = 128; st > 0; st >>= 1) { if (tid < st) red[tid] += red[tid + st]; __syncthreads(); }
        if (tid == 0) rinv_s = rsqrtf(red[0] / (float)KVLORA_ + EPS_);
        __syncthreads();
        kin[(long)t * DQK + tid] = tf32f(v * rinv_s * g_kva[tid]);
        if (tid < 16) {
            float p = (float)pos[t];
            float f = p * powf(10000.f, -(float)tid / 16.f);
            float c = cosf(f), s = sinf(f);
            float x1 = x[KVLORA_ + tid];
            float x2 = x[KVLORA_ + 16 + tid];
            kin[(long)t * DQK + KVLORA_ + tid]      = tf32f(x1 * c - x2 * s);
            kin[(long)t * DQK + KVLORA_ + 16 + tid] = tf32f(x2 * c + x1 * s);
        }
    }
    __syncthreads();

    // ---- part 2: rms768 ----
    {
        const float* x = qa + (long)t * QLORA_;
        float s = 0.f;
        for (int i = tid; i < QLORA_; i += 256) { float v = x[i]; s += v * v; }
        red[tid] = s;
        __syncthreads();
        for (int st = 128; st > 0; st >>= 1) { if (tid < st) red[tid] += red[tid + st]; __syncthreads(); }
        if (tid == 0) rinv_s = rsqrtf(red[0] / (float)QLORA_ + EPS_);
        __syncthreads();
        for (int i = tid; i < QLORA_; i += 256)
            qan[(long)t * QLORA_ + i] = tf32f(x[i] * rinv_s * g_qa[i]);
    }
}

// ---------------- RoPE q_pe ----------------
__global__ void rope_q_kernel(const float* __restrict__ q, const int* __restrict__ pos,
                              float* __restrict__ qin)
{
    int idx = blockIdx.x * blockDim.x + threadIdx.x;
    if (idx >= T_ * H_ * 16) return;
    int j = idx & 15;
    int h = (idx >> 4) % H_;
    int t = idx / (16 * H_);
    float p = (float)pos[t];
    float f = p * powf(10000.f, -(float)j / 16.f);
    float c = cosf(f), s = sinf(f);
    const float* qp = q + (long)t * (H_ * QHD) + h * QHD + NOPE_;
    float x1 = qp[j], x2 = qp[16 + j];
    float* o = qin + (long)t * (H_ * DQK) + h * DQK + KVLORA_;
    o[j]      = x1 * c - x2 * s;
    o[16 + j] = x2 * c + x1 * s;
}

// ---------------- flash attention v8b: split-half wait + KRLD=300 ----------------
#define KRLD 300
#define PLD4 68
#define QF_FLOATS (4 * 36 * 32 * 4)
#define ATTN8_SMEM ((QF_FLOATS + 64 * KRLD + 64 * PLD4 + 256 + 256 + 64 + 64) * 4)

__global__ void __launch_bounds__(256, 1)
attn8_kernel(const float* __restrict__ qin, const float* __restrict__ kin,
             float* __restrict__ olat)
{
    extern __shared__ float sm[];
    float* Qf     = sm;
    float* Kraw   = Qf + QF_FLOATS;
    float* Ps     = Kraw + 64 * KRLD;
    float* redmax = Ps + 64 * PLD4;
    float* redsum = redmax + 256;
    float* m_s    = redsum + 256;
    float* l_s    = m_s + 64;

    const int h   = blockIdx.y;
    const int qb  = gridDim.x - 1 - blockIdx.x;
    const int i0  = qb * 64;
    const int tid = threadIdx.x;
    const int w    = tid >> 5;
    const int lane = tid & 31;
    const int wm   = (w & 1) * 32;
    const int wni  = w >> 1;
    const int wn   = wni * 16;
    const int wv   = wni * 64;
    const int lq   = lane >> 2;
    const int lr   = lane & 3;
    const float scale = 0.102062072615966f;  // 1/sqrt(96)

    // ---- Q -> fragment-order smem (pre-scaled tf32) ----
    {
        const int row   = tid >> 2;
        const int dbase = (tid & 3) * 72;
        const int mg  = row >> 4;
        const int lq8 = row & 7;
        const int rb0 = (row >> 3) & 1;
        const float* src = qin + (size_t)(i0 + row) * (H_ * DQK) + h * DQK + dbase;
#pragma unroll
        for (int i = 0; i < 18; i++) {
            float4 v = *(const float4*)(src + i * 4);
            const int d0  = dbase + i * 4;
            const int d8  = d0 >> 3;
            const int reg = rb0 + ((d0 >> 2) & 1) * 2;
            float* dst = Qf + ((mg * 36 + d8) * 32 + lq8 * 4) * 4 + reg;
            dst[0]  = __uint_as_float(tf32c(v.x * scale));
            dst[4]  = __uint_as_float(tf32c(v.y * scale));
            dst[8]  = __uint_as_float(tf32c(v.z * scale));
            dst[12] = __uint_as_float(tf32c(v.w * scale));
        }
    }
    if (tid < 64) { m_s[tid] = -1e30f; l_s[tid] = 0.f; }

    float o[2][8][4];
#pragma unroll
    for (int mi = 0; mi < 2; mi++)
#pragma unroll
        for (int ni = 0; ni < 8; ni++)
#pragma unroll
            for (int r = 0; r < 4; r++) o[mi][ni][r] = 0.f;

    const unsigned kraw_s = (unsigned)__cvta_generic_to_shared(Kraw);
    const int wg    = tid >> 7;
    const int lrow  = ((tid & 127) >> 2) + wg * 32;
    const int lcol  = (tid & 3) * 72;
    const int qmg0  = 2 * (w & 1);
    const int nkb   = qb + 1;

    for (int kb = 0; kb < nkb; kb++) {
        const int j0 = kb * 64;
        __syncthreads();

        {
            const float* src = kin + (size_t)(j0 + lrow) * DQK + lcol;
            const unsigned dst = kraw_s + (unsigned)(lrow * KRLD + lcol) * 4;
#pragma unroll
            for (int i = 0; i < 18; i++)
                cp16(dst + i * 16, src + i * 4, 16);
        }
        CP_COMMIT();
        CP_WAIT(0);
        if (wg == 0) asm volatile("bar.sync 1, 128;" ::: "memory");
        else         asm volatile("bar.sync 2, 128;" ::: "memory");

        if (kb + 1 < nkb) {
            const float* p = kin + (size_t)(j0 + 64 + lrow) * DQK + lcol;
            asm volatile("prefetch.global.L2 [%0];" :: "l"(p));
            asm volatile("prefetch.global.L2 [%0];" :: "l"(p + 36));
        }

        float s[2][2][4];
#pragma unroll
        for (int mi = 0; mi < 2; mi++)
#pragma unroll
            for (int ni = 0; ni < 2; ni++)
#pragma unroll
                for (int r = 0; r < 4; r++) s[mi][ni][r] = 0.f;

#pragma unroll 4
        for (int d8 = 0; d8 < 36; d8++) {
            unsigned a[2][4];
#pragma unroll
            for (int mi = 0; mi < 2; mi++) {
                float4 qv = *(const float4*)(Qf + (((qmg0 + mi) * 36 + d8) * 32 + lane) * 4);
                a[mi][0] = __float_as_uint(qv.x); a[mi][1] = __float_as_uint(qv.y);
                a[mi][2] = __float_as_uint(qv.z); a[mi][3] = __float_as_uint(qv.w);
            }
#pragma unroll
            for (int ni = 0; ni < 2; ni++) {
                const unsigned* kp = (const unsigned*)(Kraw + (wn + 8 * ni + lq) * KRLD + d8 * 8 + lr);
                unsigned b0 = kp[0];
                unsigned b1 = kp[4];
                mma8(s[0][ni], a[0], b0, b1);
                mma8(s[1][ni], a[1], b0, b1);
            }
        }

        if (kb == qb) {
#pragma unroll
            for (int mi = 0; mi < 2; mi++)
#pragma unroll
                for (int ni = 0; ni < 2; ni++)
#pragma unroll
                    for (int r = 0; r < 4; r++) {
                        int row = wm + 16 * mi + 8 * (r >> 1) + lq;
                        int col = wn + 8 * ni + 2 * lr + (r & 1);
                        if (col > row) s[mi][ni][r] = -1e30f;
                    }
        }

#pragma unroll
        for (int mi = 0; mi < 2; mi++)
#pragma unroll
            for (int half = 0; half < 2; half++) {
                float mx = fmaxf(fmaxf(s[mi][0][2*half], s[mi][0][2*half+1]),
                                 fmaxf(s[mi][1][2*half], s[mi][1][2*half+1]));
                mx = fmaxf(mx, __shfl_xor_sync(0xffffffffu, mx, 1));
                mx = fmaxf(mx, __shfl_xor_sync(0xffffffffu, mx, 2));
                if (lr == 0) redmax[(wm + 16 * mi + 8 * half + lq) * 4 + wni] = mx;
            }
        __syncthreads();

        float alpha[2][2], mnew[2][2];
#pragma unroll
        for (int mi = 0; mi < 2; mi++)
#pragma unroll
            for (int half = 0; half < 2; half++) {
                const int row = wm + 16 * mi + 8 * half + lq;
                const float* rp = redmax + row * 4;
                float bm = fmaxf(fmaxf(rp[0], rp[1]), fmaxf(rp[2], rp[3]));
                float mo = m_s[row];
                float mn = fmaxf(mo, bm);
                mnew[mi][half]  = mn;
                alpha[mi][half] = __expf(mo - mn);
                float p0[2], p1[2];
#pragma unroll
                for (int ni = 0; ni < 2; ni++) {
                    p0[ni] = __expf(s[mi][ni][2*half]     - mn);
                    p1[ni] = __expf(s[mi][ni][2*half + 1] - mn);
                }
                float su = p0[0] + p1[0] + p0[1] + p1[1];
                su += __shfl_xor_sync(0xffffffffu, su, 1);
                su += __shfl_xor_sync(0xffffffffu, su, 2);
                if (lr == 0) redsum[row * 4 + wni] = su;
#pragma unroll
                for (int ni = 0; ni < 2; ni++) {
                    unsigned* pp = (unsigned*)(Ps + row * PLD4 + wn + 8 * ni + 2 * lr);
                    pp[0] = tf32c(p0[ni]);
                    pp[1] = tf32c(p1[ni]);
                }
            }
#pragma unroll
        for (int mi = 0; mi < 2; mi++)
#pragma unroll
            for (int ni = 0; ni < 8; ni++) {
                o[mi][ni][0] *= alpha[mi][0];
                o[mi][ni][1] *= alpha[mi][0];
                o[mi][ni][2] *= alpha[mi][1];
                o[mi][ni][3] *= alpha[mi][1];
            }
        __syncthreads();

        if (w < 2 && lr == 0) {
#pragma unroll
            for (int mi = 0; mi < 2; mi++)
#pragma unroll
                for (int half = 0; half < 2; half++) {
                    const int row = wm + 16 * mi + 8 * half + lq;
                    const float* rp = redsum + row * 4;
                    l_s[row] = l_s[row] * alpha[mi][half] + (rp[0] + rp[1] + rp[2] + rp[3]);
                    m_s[row] = mnew[mi][half];
                }
        }

#pragma unroll
        for (int kst = 0; kst < 8; kst++) {
            unsigned a[2][4];
#pragma unroll
            for (int mi = 0; mi < 2; mi++) {
                const unsigned* p0 = (const unsigned*)(Ps + (wm + 16 * mi + lq) * PLD4) + kst * 8 + lr;
                const unsigned* p1 = p0 + 8 * PLD4;
                a[mi][0] = p0[0]; a[mi][1] = p1[0]; a[mi][2] = p0[4]; a[mi][3] = p1[4];
            }
            const unsigned* vr0 = (const unsigned*)(Kraw + (kst * 8 + lr) * KRLD + wv + lq);
            const unsigned* vr1 = vr0 + 4 * KRLD;
#pragma unroll
            for (int ni = 0; ni < 8; ni++) {
                unsigned b0 = vr0[ni * 8];
                unsigned b1 = vr1[ni * 8];
                mma8(o[0][ni], a[0], b0, b1);
                mma8(o[1][ni], a[1], b0, b1);
            }
        }
    }

    __syncthreads();
#pragma unroll
    for (int mi = 0; mi < 2; mi++)
#pragma unroll
        for (int half = 0; half < 2; half++) {
            const int row = wm + 16 * mi + 8 * half + lq;
            const float linv = 1.f / l_s[row];
            float* dst = olat + (size_t)(i0 + row) * (H_ * KVLORA_) + h * KVLORA_;
#pragma unroll
            for (int ni = 0; ni < 8; ni++) {
                float2 v = make_float2(tf32f(o[mi][ni][2*half] * linv),
                                       tf32f(o[mi][ni][2*half + 1] * linv));
                *(float2*)(dst + wv + 8 * ni + 2 * lr) = v;
            }
        }
}

// ---------------- host ----------------
extern "C" void kernel_launch(void* const* d_in, const int* in_sizes, int n_in,
                              void* d_out, int out_size)
{
    const int*   positions = (const int*)  d_in[0];
    const float* hidden    = (const float*)d_in[1];
    const float* w_qa      = (const float*)d_in[2];
    const float* g_qa      = (const float*)d_in[3];
    const float* w_qb      = (const float*)d_in[4];
    const float* w_kva     = (const float*)d_in[5];
    const float* g_kva     = (const float*)d_in[6];
    const float* w_kc      = (const float*)d_in[7];
    const float* w_vc      = (const float*)d_in[8];
    const float* w_o       = (const float*)d_in[9];
    float* out = (float*)d_out;

    float *qa, *qan, *q, *lat, *kin, *qin, *olat, *ov;
    cudaGetSymbolAddress((void**)&qa,   sc_qa);
    cudaGetSymbolAddress((void**)&qan,  sc_qan);
    cudaGetSymbolAddress((void**)&q,    sc_q);
    cudaGetSymbolAddress((void**)&lat,  sc_lat);
    cudaGetSymbolAddress((void**)&kin,  sc_kin);
    cudaGetSymbolAddress((void**)&qin,  sc_qin);
    cudaGetSymbolAddress((void**)&olat, sc_olat);
    cudaGetSymbolAddress((void**)&ov,   sc_ov);

    cudaFuncSetAttribute(attn8_kernel, cudaFuncAttributeMaxDynamicSharedMemorySize, ATTN8_SMEM);
    cudaFuncSetAttribute((const void*)tgemm_ca<64,128,false,true>,   cudaFuncAttributeMaxDynamicSharedMemorySize, GEMM_SMEM(64,128));
    cudaFuncSetAttribute((const void*)tgemm_ca<64,128,true,false>,   cudaFuncAttributeMaxDynamicSharedMemorySize, GEMM_SMEM(64,128));
    cudaFuncSetAttribute((const void*)tgemm_ca<64,128,false,false>,  cudaFuncAttributeMaxDynamicSharedMemorySize, GEMM_SMEM(64,128));
    cudaFuncSetAttribute((const void*)tgemm_ca<128,128,false,false>, cudaFuncAttributeMaxDynamicSharedMemorySize, GEMM_SMEM(128,128));
    cudaFuncSetAttribute((const void*)tgemm_ca<128,64,true,false>,   cudaFuncAttributeMaxDynamicSharedMemorySize, GEMM_SMEM(128,64));

    dim3 thr(256);

    // 1+4) DUAL: z=0 -> qa = hidden @ w_qa ; z=1 -> lat = hidden @ w_kva (288 CTAs ~ 1 wave)
    tgemm_ca<64,128,false,true><<<dim3(QLORA_/128, T_/64, 2), thr, GEMM_SMEM(64,128)>>>(
        hidden, w_qa, qa,
        T_, QLORA_, HID_, HID_, QLORA_, QLORA_, 0, 0, 0,
        w_kva, lat, DQK, DQK, DQK);
    // 2+5) fused rmsnorm + latent->kin
    norm_fused_kernel<<<T_, thr>>>(qa, g_qa, qan, lat, g_kva, positions, kin);
    // 3) q = qan @ w_qb (round C) — BM=64: 960 CTAs, better wave quantization
    tgemm_ca<64,128,true,false><<<dim3((H_*QHD)/128, T_/64, 1), thr, GEMM_SMEM(64,128)>>>(
        qan, w_qb, q,
        T_, H_*QHD, QLORA_, QLORA_, H_*QHD, H_*QHD, 0, 0, 0,
        nullptr, nullptr, 0, 0, 0);
    // 6) q_lat batched over heads
    tgemm_ca<128,128,false,false><<<dim3(KVLORA_/128, T_/128, H_), thr, GEMM_SMEM(128,128)>>>(
        q, w_kc, qin,
        T_, KVLORA_, NOPE_, H_*QHD, KVLORA_, H_*DQK,
        (long)QHD, (long)NOPE_*KVLORA_, (long)DQK,
        nullptr, nullptr, 0, 0, 0);
    // 7) rope q_pe
    rope_q_kernel<<<(T_*H_*16 + 255)/256, thr>>>(q, positions, qin);
    // 8) attention (attn8: best-known)
    attn8_kernel<<<dim3(T_/64, H_), thr, ATTN8_SMEM>>>(qin, kin, olat);
    // 9) v-proj batched
    tgemm_ca<128,64,true,false><<<dim3(1, T_/128, H_), thr, GEMM_SMEM(128,64)>>>(
        olat, w_vc, ov,
        T_, VDIM_, KVLORA_, H_*KVLORA_, VDIM_, H_*VDIM_,
        (long)KVLORA_, (long)KVLORA_*VDIM_, (long)VDIM_,
        nullptr, nullptr, 0, 0, 0);
    // 10) out = ov @ w_o — BM=64: 640 CTAs, kills the 320-CTA wave tail
    tgemm_ca<64,128,false,false><<<dim3(HID_/128, T_/64, 1), thr, GEMM_SMEM(64,128)>>>(
        ov, w_o, out,
        T_, HID_, H_*VDIM_, H_*VDIM_, HID_, HID_, 0, 0, 0,
        nullptr, nullptr, 0, 0, 0);
}